// round 1
// baseline (speedup 1.0000x reference)
#include <cuda_runtime.h>

#define NT   256
#define SPB  2      // samples per block
#define NP   20     // N_PERM
#define KT_LD 21    // padded leading dim for transposed K

__global__ __launch_bounds__(NT, 1)
void actor_kernel(
    const float* __restrict__ obs, const float* __restrict__ ag, const float* __restrict__ g,
    const float* __restrict__ W1, const float* __restrict__ b1,
    const float* __restrict__ W2, const float* __restrict__ b2,
    const float* __restrict__ Wq, const float* __restrict__ bq,
    const float* __restrict__ Wk, const float* __restrict__ bk,
    const float* __restrict__ Wv, const float* __restrict__ bv,
    const float* __restrict__ Wr, const float* __restrict__ br,
    const float* __restrict__ Wm, const float* __restrict__ bm,
    const float* __restrict__ Ws, const float* __restrict__ bs,
    const int* __restrict__ edges, const int* __restrict__ pred_ids,
    float* __restrict__ out, int B)
{
    extern __shared__ float sm[];
    float* s_inp  = sm;                       // SPB*20*20 = 800
    float* s_h    = s_inp + 800;              // SPB*20*256 = 10240
    float* s_ef   = s_h + 10240;              // SPB*20*128 = 5120
    float* s_q    = s_ef + 5120;              // 5120
    float* s_kT   = s_q + 5120;               // SPB*128*21 = 5376
    float* s_v    = s_kT + 5376;              // 5120
    float* s_sc   = s_v + 5120;               // SPB*20*20 = 800
    float* s_colw = s_sc + 800;               // 48
    float* s_pool = s_colw + 48;              // SPB*128 = 256
    float* s_hr   = s_pool + 256;             // SPB*256 = 512
    float* s_obs  = s_hr + 512;               // SPB*88 = 176
    float* s_dg   = s_obs + 176;              // SPB*32 = 64
    float* s_wbuf = s_dg + 64;                // 8192
    int*   s_edge = (int*)(s_wbuf + 8192);    // 40
    int*   s_pred = s_edge + 40;              // 60

    const int tid = threadIdx.x;
    const int b0  = blockIdx.x * SPB;

    // ---------------- Stage 0: load inputs, build inp_mp, stage W1 ----------------
    for (int i = tid; i < SPB*85; i += NT) {
        int s = i / 85, c = i - 85*s;
        s_obs[s*88 + c] = obs[(size_t)(b0+s)*85 + c];
    }
    for (int i = tid; i < SPB*30; i += NT) {
        int s = i / 30, c = i - 30*s;
        s_dg[s*32 + c] = g[(size_t)(b0+s)*30 + c] - ag[(size_t)(b0+s)*30 + c];
    }
    if (tid < 40) s_edge[tid] = edges[tid];
    if (tid < 60) s_pred[tid] = pred_ids[tid];
    for (int i = tid; i < 19*256; i += NT) s_wbuf[i] = W1[i];
    __syncthreads();

    for (int i = tid; i < SPB*NP*19; i += NT) {
        int s = i / (NP*19); int rem = i - s*NP*19;
        int p = rem / 19;    int c = rem - 19*p;
        float val;
        if (c < 10)      val = s_obs[s*88 + c];
        else if (c < 13) val = s_dg[s*32 + s_pred[p*3 + (c-10)]];
        else if (c < 16) val = s_obs[s*88 + 10 + s_edge[p*2]   * 15 + (c-13)];
        else             val = s_obs[s*88 + 10 + s_edge[p*2+1] * 15 + (c-16)];
        s_inp[(s*NP + p)*20 + c] = val;
    }
    __syncthreads();

    // ---------------- Stage 1: h = relu(inp @ W1 + b1), thread = output column ----
    {
        float w1c[19];
        #pragma unroll
        for (int c = 0; c < 19; c++) w1c[c] = s_wbuf[c*256 + tid];
        const float bb = b1[tid];
        #pragma unroll 4
        for (int sp = 0; sp < SPB*NP; sp++) {
            float acc = bb;
            #pragma unroll
            for (int c = 0; c < 19; c++) acc = fmaf(s_inp[sp*20 + c], w1c[c], acc);
            s_h[sp*256 + tid] = fmaxf(acc, 0.f);
        }
    }
    __syncthreads();

    const int jp  = tid & 63;   // float2 column pair (j = 2*jp, 2*jp+1)
    const int grp = tid >> 6;   // 4 row-groups of 10 rows

    // ---------------- Stage 2: ef = relu(h @ W2 + b2), K=256 in 4 chunks ----------
    {
        float2 acc[10];
        float2 bp = *(const float2*)&b2[2*jp];
        #pragma unroll
        for (int r = 0; r < 10; r++) acc[r] = bp;
        for (int kc = 0; kc < 4; kc++) {
            for (int i = tid; i < 8192; i += NT) s_wbuf[i] = W2[kc*8192 + i];
            __syncthreads();
            #pragma unroll 4
            for (int k2 = 0; k2 < 64; k2 += 2) {
                float2 wa = *(const float2*)&s_wbuf[ k2     *128 + 2*jp];
                float2 wb = *(const float2*)&s_wbuf[(k2+1)*128 + 2*jp];
                #pragma unroll
                for (int r = 0; r < 10; r++) {
                    int pi = grp*10 + r;
                    float2 hv = *(const float2*)&s_h[pi*256 + kc*64 + k2];
                    acc[r].x = fmaf(hv.x, wa.x, acc[r].x);
                    acc[r].y = fmaf(hv.x, wa.y, acc[r].y);
                    acc[r].x = fmaf(hv.y, wb.x, acc[r].x);
                    acc[r].y = fmaf(hv.y, wb.y, acc[r].y);
                }
            }
            __syncthreads();
        }
        #pragma unroll
        for (int r = 0; r < 10; r++) {
            int pi = grp*10 + r;
            float2 v2; v2.x = fmaxf(acc[r].x, 0.f); v2.y = fmaxf(acc[r].y, 0.f);
            *(float2*)&s_ef[pi*128 + 2*jp] = v2;
        }
    }
    __syncthreads();

    // ---------------- Stage 3: q / kT / v = ef @ W{q,k,v} + b, K=128 -------------
    {
        const float* Wmat[3] = {Wq, Wk, Wv};
        const float* bvec[3] = {bq, bk, bv};
        for (int m = 0; m < 3; m++) {
            float2 acc[10];
            float2 bp = *(const float2*)&bvec[m][2*jp];
            #pragma unroll
            for (int r = 0; r < 10; r++) acc[r] = bp;
            for (int kc = 0; kc < 2; kc++) {
                for (int i = tid; i < 8192; i += NT) s_wbuf[i] = Wmat[m][kc*8192 + i];
                __syncthreads();
                #pragma unroll 4
                for (int k2 = 0; k2 < 64; k2 += 2) {
                    float2 wa = *(const float2*)&s_wbuf[ k2     *128 + 2*jp];
                    float2 wb = *(const float2*)&s_wbuf[(k2+1)*128 + 2*jp];
                    #pragma unroll
                    for (int r = 0; r < 10; r++) {
                        int pi = grp*10 + r;
                        float2 hv = *(const float2*)&s_ef[pi*128 + kc*64 + k2];
                        acc[r].x = fmaf(hv.x, wa.x, acc[r].x);
                        acc[r].y = fmaf(hv.x, wa.y, acc[r].y);
                        acc[r].x = fmaf(hv.y, wb.x, acc[r].x);
                        acc[r].y = fmaf(hv.y, wb.y, acc[r].y);
                    }
                }
                __syncthreads();
            }
            if (m == 0) {
                #pragma unroll
                for (int r = 0; r < 10; r++) {
                    int pi = grp*10 + r;
                    *(float2*)&s_q[pi*128 + 2*jp] = acc[r];
                }
            } else if (m == 2) {
                #pragma unroll
                for (int r = 0; r < 10; r++) {
                    int pi = grp*10 + r;
                    *(float2*)&s_v[pi*128 + 2*jp] = acc[r];
                }
            } else {  // K: store transposed for conflict-free score loads
                #pragma unroll
                for (int r = 0; r < 10; r++) {
                    int pi = grp*10 + r;
                    int s = pi / NP, p = pi - NP*s;
                    s_kT[(s*128 + 2*jp    )*KT_LD + p] = acc[r].x;
                    s_kT[(s*128 + 2*jp + 1)*KT_LD + p] = acc[r].y;
                }
            }
        }
    }
    __syncthreads();

    // ---------------- Stage 4: scores = q @ kT / sqrt(128) ------------------------
    for (int i = tid; i < SPB*NP*NP; i += NT) {
        int s = i / (NP*NP); int rem = i - s*NP*NP;
        int p = rem / NP;    int r = rem - NP*p;
        const float* qrow = &s_q[(s*NP + p)*128];
        float acc = 0.f;
        #pragma unroll
        for (int d = 0; d < 128; d += 4) {
            float4 q4 = *(const float4*)&qrow[d];
            acc = fmaf(q4.x, s_kT[(s*128 + d    )*KT_LD + r], acc);
            acc = fmaf(q4.y, s_kT[(s*128 + d + 1)*KT_LD + r], acc);
            acc = fmaf(q4.z, s_kT[(s*128 + d + 2)*KT_LD + r], acc);
            acc = fmaf(q4.w, s_kT[(s*128 + d + 3)*KT_LD + r], acc);
        }
        s_sc[i] = acc * 0.088388347648318447f;  // 1/sqrt(128)
    }
    __syncthreads();

    // ---------------- Stage 5: softmax rows + column weights ----------------------
    if (tid < SPB*NP) {
        float* row = &s_sc[tid*NP];
        float mx = row[0];
        #pragma unroll
        for (int r = 1; r < NP; r++) mx = fmaxf(mx, row[r]);
        float sum = 0.f;
        #pragma unroll
        for (int r = 0; r < NP; r++) { float e = __expf(row[r] - mx); row[r] = e; sum += e; }
        float inv = 1.f / sum;
        #pragma unroll
        for (int r = 0; r < NP; r++) row[r] *= inv;
    }
    __syncthreads();
    if (tid < SPB*NP) {  // colw[s][r] = sum_p attn[s][p][r]  (pooling over p folded in)
        int s = tid / NP, r = tid - NP*s;
        float acc = 0.f;
        #pragma unroll
        for (int p = 0; p < NP; p++) acc += s_sc[(s*NP + p)*NP + r];
        s_colw[s*NP + r] = acc;
    }
    __syncthreads();

    // ---------------- Stage 6: pooled = colw @ v -----------------------------------
    {
        int s = tid >> 7, d = tid & 127;
        float acc = 0.f;
        #pragma unroll
        for (int r = 0; r < NP; r++) acc = fmaf(s_colw[s*NP + r], s_v[(s*NP + r)*128 + d], acc);
        s_pool[s*128 + d] = acc;
    }
    __syncthreads();

    // ---------------- Stage 7: hr = relu(pooled @ Wr + br) ------------------------
    {
        float a0 = br[tid], a1 = a0;
        #pragma unroll 8
        for (int d = 0; d < 128; d++) {
            float w = Wr[d*256 + tid];
            a0 = fmaf(s_pool[d],       w, a0);
            a1 = fmaf(s_pool[128 + d], w, a1);
        }
        s_hr[tid]       = fmaxf(a0, 0.f);
        s_hr[256 + tid] = fmaxf(a1, 0.f);
    }
    __syncthreads();

    // ---------------- Stage 8: heads (mean / clipped log_std) ---------------------
    {
        int w = tid >> 5, lane = tid & 31;
        for (int o = w; o < 16; o += 8) {
            int s = o >> 3, head = (o >> 2) & 1, a = o & 3;
            const float* Wh = head ? Ws : Wm;
            float acc = 0.f;
            #pragma unroll
            for (int j = lane; j < 256; j += 32)
                acc = fmaf(s_hr[s*256 + j], Wh[j*4 + a], acc);
            #pragma unroll
            for (int off = 16; off > 0; off >>= 1)
                acc += __shfl_xor_sync(0xffffffffu, acc, off);
            if (lane == 0) {
                float val = acc + (head ? bs[a] : bm[a]);
                size_t bg = (size_t)(b0 + s);
                if (head) {
                    val = fminf(fmaxf(val, -20.f), 2.f);
                    out[(size_t)B*4 + bg*4 + a] = val;
                } else {
                    out[bg*4 + a] = val;
                }
            }
        }
    }
}

extern "C" void kernel_launch(void* const* d_in, const int* in_sizes, int n_in,
                              void* d_out, int out_size) {
    const float* obs = (const float*)d_in[0];
    const float* ag  = (const float*)d_in[1];
    const float* g   = (const float*)d_in[2];
    const float* W1  = (const float*)d_in[3];
    const float* b1  = (const float*)d_in[4];
    const float* W2  = (const float*)d_in[5];
    const float* b2  = (const float*)d_in[6];
    const float* Wq  = (const float*)d_in[7];
    const float* bq  = (const float*)d_in[8];
    const float* Wk  = (const float*)d_in[9];
    const float* bk  = (const float*)d_in[10];
    const float* Wv  = (const float*)d_in[11];
    const float* bv  = (const float*)d_in[12];
    const float* Wr  = (const float*)d_in[13];
    const float* br  = (const float*)d_in[14];
    const float* Wm  = (const float*)d_in[15];
    const float* bm  = (const float*)d_in[16];
    const float* Ws  = (const float*)d_in[17];
    const float* bs  = (const float*)d_in[18];
    const int* edges    = (const int*)d_in[19];
    const int* pred_ids = (const int*)d_in[20];
    float* out = (float*)d_out;

    const int B = in_sizes[0] / 85;
    // smem: 41824 floats + 100 ints = 167,696 bytes
    const size_t smem = (size_t)(800+10240+5120+5120+5376+5120+800+48+256+512+176+64+8192)*4 + 100*4;
    cudaFuncSetAttribute(actor_kernel, cudaFuncAttributeMaxDynamicSharedMemorySize, (int)smem);

    actor_kernel<<<B / SPB, NT, smem>>>(
        obs, ag, g, W1, b1, W2, b2, Wq, bq, Wk, bk, Wv, bv,
        Wr, br, Wm, bm, Ws, bs, edges, pred_ids, out, B);
}

// round 2
// speedup vs baseline: 1.7396x; 1.7396x over previous
#include <cuda_runtime.h>

#define NT    256
#define SPB   2
#define NP    20
#define ROWS  40
#define HT_LD 44

typedef unsigned long long u64t;

__device__ __forceinline__ u64t ffma2(u64t a, u64t b, u64t c) {
    u64t d;
    asm("fma.rn.f32x2 %0, %1, %2, %3;" : "=l"(d) : "l"(a), "l"(b), "l"(c));
    return d;
}
__device__ __forceinline__ u64t dup2(float x) {
    u64t d;
    asm("mov.b64 %0, {%1, %1};" : "=l"(d) : "f"(x));
    return d;
}
__device__ __forceinline__ float2 unpk(u64t a) {
    float2 r;
    asm("mov.b64 {%0, %1}, %2;" : "=f"(r.x), "=f"(r.y) : "l"(a));
    return r;
}

__global__ __launch_bounds__(NT, 2)
void actor_kernel(
    const float* __restrict__ obs, const float* __restrict__ ag, const float* __restrict__ g,
    const float* __restrict__ W1, const float* __restrict__ b1,
    const float* __restrict__ W2, const float* __restrict__ b2,
    const float* __restrict__ Wq, const float* __restrict__ bq,
    const float* __restrict__ Wk, const float* __restrict__ bk,
    const float* __restrict__ Wv, const float* __restrict__ bv,
    const float* __restrict__ Wr, const float* __restrict__ br,
    const float* __restrict__ Wm, const float* __restrict__ bm,
    const float* __restrict__ Ws, const float* __restrict__ bs,
    const int* __restrict__ edges, const int* __restrict__ pred_ids,
    float* __restrict__ out, int B)
{
    extern __shared__ float sm[];
    float* s_inp  = sm;            // 800   (40 x 20)
    float* s_hT   = sm + 800;      // 2816  (64 x 44) transposed h chunk
    float* s_sc   = sm + 800;      // 800   overlay (hT dead after stage2)
    float* s_colw = sm + 1600;     // 48
    float* s_pool = sm + 1648;     // 256
    float* s_hr   = sm + 1904;     // 512
    float* s_efT  = sm + 3616;     // 5632  (128 x 44) transposed ef
    float* s_v    = sm + 3616;     // 5120  overlay (efT dead when v written)
    float* s_q    = sm + 9248;     // 5120  (40 x 128) row-major
    float* s_k    = sm + 14368;    // 5120  (40 x 128) row-major
    float* s_obs  = sm + 19488;    // 176
    float* s_dg   = sm + 19664;    // 64
    float* s_wbuf = sm + 19728;    // 8192  (64 x 128) weight chunk
    int*   s_edge = (int*)(sm + 27920);  // 40
    int*   s_pred = s_edge + 40;         // 60   -> total 28020 f + 100 i

    const int tid = threadIdx.x;
    const int b0  = blockIdx.x * SPB;

    // ---------- Stage 0: inputs ----------
    for (int i = tid; i < SPB*85; i += NT) {
        int s = i / 85, c = i - 85*s;
        s_obs[s*88 + c] = obs[(size_t)(b0+s)*85 + c];
    }
    for (int i = tid; i < SPB*30; i += NT) {
        int s = i / 30, c = i - 30*s;
        s_dg[s*32 + c] = g[(size_t)(b0+s)*30 + c] - ag[(size_t)(b0+s)*30 + c];
    }
    if (tid < 40) s_edge[tid] = edges[tid];
    if (tid < 60) s_pred[tid] = pred_ids[tid];
    __syncthreads();

    for (int i = tid; i < SPB*NP*19; i += NT) {
        int s = i / (NP*19); int rem = i - s*NP*19;
        int p = rem / 19;    int c = rem - 19*p;
        float val;
        if (c < 10)      val = s_obs[s*88 + c];
        else if (c < 13) val = s_dg[s*32 + s_pred[p*3 + (c-10)]];
        else if (c < 16) val = s_obs[s*88 + 10 + s_edge[p*2]   * 15 + (c-13)];
        else             val = s_obs[s*88 + 10 + s_edge[p*2+1] * 15 + (c-16)];
        s_inp[(s*NP + p)*20 + c] = val;
    }
    __syncthreads();

    const int col = tid & 127;     // output column (stage2/3)
    const int g2  = tid >> 7;      // row half: rows g2*20 .. +19
    const int hc  = tid & 63;      // h column within chunk (stage1)
    const int g1  = tid >> 6;      // row quarter: rows g1*10 .. +9

    // ---------- Stage 1+2 fused: ef = relu(relu(inp@W1+b1) @ W2 + b2) ----------
    u64t acc[10];
    {
        float bcol = b2[col];
        #pragma unroll
        for (int j = 0; j < 10; j++) acc[j] = dup2(bcol);
    }
    for (int cc = 0; cc < 4; cc++) {
        // stage1: build transposed h chunk hT[k=0..63][row=0..39]
        {
            float w1r[19];
            #pragma unroll
            for (int c = 0; c < 19; c++) w1r[c] = W1[c*256 + cc*64 + hc];
            float bb = b1[cc*64 + hc];
            #pragma unroll
            for (int r = 0; r < 10; r++) {
                int row = g1*10 + r;
                const float4* ip = (const float4*)(s_inp + row*20);
                float4 i0 = ip[0], i1 = ip[1], i2 = ip[2], i3 = ip[3], i4 = ip[4];
                float a = bb;
                a = fmaf(i0.x, w1r[0], a);  a = fmaf(i0.y, w1r[1], a);
                a = fmaf(i0.z, w1r[2], a);  a = fmaf(i0.w, w1r[3], a);
                a = fmaf(i1.x, w1r[4], a);  a = fmaf(i1.y, w1r[5], a);
                a = fmaf(i1.z, w1r[6], a);  a = fmaf(i1.w, w1r[7], a);
                a = fmaf(i2.x, w1r[8], a);  a = fmaf(i2.y, w1r[9], a);
                a = fmaf(i2.z, w1r[10], a); a = fmaf(i2.w, w1r[11], a);
                a = fmaf(i3.x, w1r[12], a); a = fmaf(i3.y, w1r[13], a);
                a = fmaf(i3.z, w1r[14], a); a = fmaf(i3.w, w1r[15], a);
                a = fmaf(i4.x, w1r[16], a); a = fmaf(i4.y, w1r[17], a);
                a = fmaf(i4.z, w1r[18], a);
                s_hT[hc*HT_LD + row] = fmaxf(a, 0.f);
            }
        }
        // stage W2 chunk into smem
        {
            const float4* src = (const float4*)(W2 + cc*8192);
            float4* dst = (float4*)s_wbuf;
            #pragma unroll
            for (int i = 0; i < 8; i++) dst[tid + i*256] = src[tid + i*256];
        }
        __syncthreads();
        // stage2 accumulate: 64 k-steps, FFMA2 over row-pairs
        #pragma unroll 4
        for (int k = 0; k < 64; k++) {
            u64t wd = dup2(s_wbuf[k*128 + col]);
            const ulonglong2* hp = (const ulonglong2*)(s_hT + k*HT_LD + g2*20);
            ulonglong2 u0 = hp[0], u1 = hp[1], u2 = hp[2], u3 = hp[3], u4 = hp[4];
            acc[0] = ffma2(u0.x, wd, acc[0]); acc[1] = ffma2(u0.y, wd, acc[1]);
            acc[2] = ffma2(u1.x, wd, acc[2]); acc[3] = ffma2(u1.y, wd, acc[3]);
            acc[4] = ffma2(u2.x, wd, acc[4]); acc[5] = ffma2(u2.y, wd, acc[5]);
            acc[6] = ffma2(u3.x, wd, acc[6]); acc[7] = ffma2(u3.y, wd, acc[7]);
            acc[8] = ffma2(u4.x, wd, acc[8]); acc[9] = ffma2(u4.y, wd, acc[9]);
        }
        __syncthreads();
    }
    // store ef transposed with relu
    #pragma unroll
    for (int j = 0; j < 10; j++) {
        float2 e = unpk(acc[j]);
        e.x = fmaxf(e.x, 0.f); e.y = fmaxf(e.y, 0.f);
        *(float2*)(s_efT + col*HT_LD + g2*20 + 2*j) = e;
    }
    __syncthreads();

    // ---------- Stage 3: q/k/v = ef @ W{q,k,v} + b ----------
    for (int m = 0; m < 3; m++) {
        const float* Wmat = (m == 0) ? Wq : ((m == 1) ? Wk : Wv);
        const float* bvec = (m == 0) ? bq : ((m == 1) ? bk : bv);
        u64t qa[10];
        {
            float bcol = bvec[col];
            #pragma unroll
            for (int j = 0; j < 10; j++) qa[j] = dup2(bcol);
        }
        for (int kc = 0; kc < 2; kc++) {
            const float4* src = (const float4*)(Wmat + kc*8192);
            float4* dst = (float4*)s_wbuf;
            #pragma unroll
            for (int i = 0; i < 8; i++) dst[tid + i*256] = src[tid + i*256];
            __syncthreads();
            #pragma unroll 4
            for (int k = 0; k < 64; k++) {
                u64t wd = dup2(s_wbuf[k*128 + col]);
                const ulonglong2* ep = (const ulonglong2*)(s_efT + (kc*64 + k)*HT_LD + g2*20);
                ulonglong2 u0 = ep[0], u1 = ep[1], u2 = ep[2], u3 = ep[3], u4 = ep[4];
                qa[0] = ffma2(u0.x, wd, qa[0]); qa[1] = ffma2(u0.y, wd, qa[1]);
                qa[2] = ffma2(u1.x, wd, qa[2]); qa[3] = ffma2(u1.y, wd, qa[3]);
                qa[4] = ffma2(u2.x, wd, qa[4]); qa[5] = ffma2(u2.y, wd, qa[5]);
                qa[6] = ffma2(u3.x, wd, qa[6]); qa[7] = ffma2(u3.y, wd, qa[7]);
                qa[8] = ffma2(u4.x, wd, qa[8]); qa[9] = ffma2(u4.y, wd, qa[9]);
            }
            __syncthreads();
        }
        // store row-major (for m==2, v overlays efT; all reads done at last sync)
        float* dst = (m == 0) ? s_q : ((m == 1) ? s_k : s_v);
        #pragma unroll
        for (int j = 0; j < 10; j++) {
            float2 e = unpk(qa[j]);
            dst[(g2*20 + 2*j    )*128 + col] = e.x;
            dst[(g2*20 + 2*j + 1)*128 + col] = e.y;
        }
    }
    __syncthreads();

    // ---------- Stage 4: scores = q @ k^T / sqrt(128), 2x2 tiles ----------
    if (tid < 200) {
        int s  = tid / 100, t2 = tid % 100;
        int p0 = (t2 / 10) * 2, r0 = (t2 % 10) * 2;
        const u64t* qA = (const u64t*)(s_q + (s*20 + p0)*128);
        const u64t* qB = (const u64t*)(s_q + (s*20 + p0 + 1)*128);
        const u64t* kA = (const u64t*)(s_k + (s*20 + r0)*128);
        const u64t* kB = (const u64t*)(s_k + (s*20 + r0 + 1)*128);
        u64t a00 = 0ull, a01 = 0ull, a10 = 0ull, a11 = 0ull;
        #pragma unroll 8
        for (int i = 0; i < 64; i++) {
            u64t q0 = qA[i], q1 = qB[i], k0 = kA[i], k1 = kB[i];
            a00 = ffma2(q0, k0, a00); a01 = ffma2(q0, k1, a01);
            a10 = ffma2(q1, k0, a10); a11 = ffma2(q1, k1, a11);
        }
        const float scl = 0.088388347648318447f;  // 1/sqrt(128)
        float2 f;
        f = unpk(a00); s_sc[(s*20 + p0    )*NP + r0    ] = (f.x + f.y) * scl;
        f = unpk(a01); s_sc[(s*20 + p0    )*NP + r0 + 1] = (f.x + f.y) * scl;
        f = unpk(a10); s_sc[(s*20 + p0 + 1)*NP + r0    ] = (f.x + f.y) * scl;
        f = unpk(a11); s_sc[(s*20 + p0 + 1)*NP + r0 + 1] = (f.x + f.y) * scl;
    }
    __syncthreads();

    // ---------- Stage 5: softmax rows + column sums (pool folded) ----------
    if (tid < SPB*NP) {
        float* row = &s_sc[tid*NP];
        float mx = row[0];
        #pragma unroll
        for (int r = 1; r < NP; r++) mx = fmaxf(mx, row[r]);
        float sum = 0.f;
        #pragma unroll
        for (int r = 0; r < NP; r++) { float e = __expf(row[r] - mx); row[r] = e; sum += e; }
        float inv = 1.f / sum;
        #pragma unroll
        for (int r = 0; r < NP; r++) row[r] *= inv;
    }
    __syncthreads();
    if (tid < SPB*NP) {
        int s = tid / NP, r = tid - NP*s;
        float a = 0.f;
        #pragma unroll
        for (int p = 0; p < NP; p++) a += s_sc[(s*NP + p)*NP + r];
        s_colw[tid] = a;
    }
    __syncthreads();

    // ---------- Stage 6: pooled = colw @ v ----------
    {
        int s = tid >> 7, d = tid & 127;
        float a = 0.f;
        #pragma unroll
        for (int r = 0; r < NP; r++) a = fmaf(s_colw[s*NP + r], s_v[(s*NP + r)*128 + d], a);
        s_pool[s*128 + d] = a;
    }
    __syncthreads();

    // ---------- Stage 7: hr = relu(pooled @ Wr + br) ----------
    {
        float a0 = br[tid], a1 = a0;
        #pragma unroll 8
        for (int d = 0; d < 128; d++) {
            float w = Wr[d*256 + tid];
            a0 = fmaf(s_pool[d],       w, a0);
            a1 = fmaf(s_pool[128 + d], w, a1);
        }
        s_hr[tid]       = fmaxf(a0, 0.f);
        s_hr[256 + tid] = fmaxf(a1, 0.f);
    }
    __syncthreads();

    // ---------- Stage 8: heads ----------
    {
        int w = tid >> 5, lane = tid & 31;
        for (int o = w; o < 16; o += 8) {
            int s = o >> 3, head = (o >> 2) & 1, a = o & 3;
            const float* Wh = head ? Ws : Wm;
            float acc8 = 0.f;
            #pragma unroll
            for (int j = lane; j < 256; j += 32)
                acc8 = fmaf(s_hr[s*256 + j], Wh[j*4 + a], acc8);
            #pragma unroll
            for (int off = 16; off > 0; off >>= 1)
                acc8 += __shfl_xor_sync(0xffffffffu, acc8, off);
            if (lane == 0) {
                float val = acc8 + (head ? bs[a] : bm[a]);
                size_t bg = (size_t)(b0 + s);
                if (head) {
                    val = fminf(fmaxf(val, -20.f), 2.f);
                    out[(size_t)B*4 + bg*4 + a] = val;
                } else {
                    out[bg*4 + a] = val;
                }
            }
        }
    }
}

extern "C" void kernel_launch(void* const* d_in, const int* in_sizes, int n_in,
                              void* d_out, int out_size) {
    const float* obs = (const float*)d_in[0];
    const float* ag  = (const float*)d_in[1];
    const float* g   = (const float*)d_in[2];
    const float* W1  = (const float*)d_in[3];
    const float* b1  = (const float*)d_in[4];
    const float* W2  = (const float*)d_in[5];
    const float* b2  = (const float*)d_in[6];
    const float* Wq  = (const float*)d_in[7];
    const float* bq  = (const float*)d_in[8];
    const float* Wk  = (const float*)d_in[9];
    const float* bk  = (const float*)d_in[10];
    const float* Wv  = (const float*)d_in[11];
    const float* bv  = (const float*)d_in[12];
    const float* Wr  = (const float*)d_in[13];
    const float* br  = (const float*)d_in[14];
    const float* Wm  = (const float*)d_in[15];
    const float* bm  = (const float*)d_in[16];
    const float* Ws  = (const float*)d_in[17];
    const float* bs  = (const float*)d_in[18];
    const int* edges    = (const int*)d_in[19];
    const int* pred_ids = (const int*)d_in[20];
    float* out = (float*)d_out;

    const int B = in_sizes[0] / 85;
    const size_t smem = (size_t)(28020 + 100) * 4;  // 112,480 B -> 2 blocks/SM
    cudaFuncSetAttribute(actor_kernel, cudaFuncAttributeMaxDynamicSharedMemorySize, (int)smem);

    actor_kernel<<<B / SPB, NT, smem>>>(
        obs, ag, g, W1, b1, W2, b2, Wq, bq, Wk, bk, Wv, bv,
        Wr, br, Wm, bm, Ws, bs, edges, pred_ids, out, B);
}

// round 3
// speedup vs baseline: 2.1038x; 1.2093x over previous
#include <cuda_runtime.h>

#define NT   256
#define SPB  2
#define NP   20
#define LD   52     // hT/efT leading dim; rows in 4 groups of 10 at 12-slot stride

typedef unsigned long long u64t;

__device__ __forceinline__ u64t ffma2(u64t a, u64t b, u64t c) {
    u64t d;
    asm("fma.rn.f32x2 %0, %1, %2, %3;" : "=l"(d) : "l"(a), "l"(b), "l"(c));
    return d;
}
__device__ __forceinline__ u64t add2(u64t a, u64t b) {
    u64t d;
    asm("add.rn.f32x2 %0, %1, %2;" : "=l"(d) : "l"(a), "l"(b));
    return d;
}
__device__ __forceinline__ u64t dup2(float x) {
    u64t d;
    asm("mov.b64 %0, {%1, %1};" : "=l"(d) : "f"(x));
    return d;
}
__device__ __forceinline__ float2 unpk(u64t a) {
    float2 r;
    asm("mov.b64 {%0, %1}, %2;" : "=f"(r.x), "=f"(r.y) : "l"(a));
    return r;
}

// smem float offsets
#define OFF_INP   0        // 800  (40 x 20)
#define OFF_HT    800      // 1664 (32 x 52)   [overlay: sc 800, colw 48, pool 256]
#define OFF_EFT   2464     // 6656 (128 x 52)  [overlay: v 5120]
#define OFF_Q     9120     // 5120
#define OFF_K     14240    // 5120
#define OFF_WBUF  19360    // 8192
#define OFF_OBS   27552    // 176
#define OFF_DG    27728    // 64
#define OFF_INT   27792    // 100 ints
#define SMEM_ELEMS 27892
// overlays
#define OFF_SC    OFF_HT          // 800
#define OFF_COLW  (OFF_HT + 800)  // 48
#define OFF_POOL  (OFF_HT + 848)  // 256
#define OFF_HR    0               // 512 (over inp)
#define OFF_V     OFF_EFT         // 5120 (over efT)

__global__ __launch_bounds__(NT, 2)
void actor_kernel(
    const float* __restrict__ obs, const float* __restrict__ ag, const float* __restrict__ g,
    const float* __restrict__ W1, const float* __restrict__ b1,
    const float* __restrict__ W2, const float* __restrict__ b2,
    const float* __restrict__ Wq, const float* __restrict__ bq,
    const float* __restrict__ Wk, const float* __restrict__ bk,
    const float* __restrict__ Wv, const float* __restrict__ bv,
    const float* __restrict__ Wr, const float* __restrict__ br,
    const float* __restrict__ Wm, const float* __restrict__ bm,
    const float* __restrict__ Ws, const float* __restrict__ bs,
    const int* __restrict__ edges, const int* __restrict__ pred_ids,
    float* __restrict__ out, int B)
{
    extern __shared__ float sm[];
    float* s_inp  = sm + OFF_INP;
    float* s_hT   = sm + OFF_HT;
    float* s_efT  = sm + OFF_EFT;
    float* s_q    = sm + OFF_Q;
    float* s_kk   = sm + OFF_K;
    float* s_wbuf = sm + OFF_WBUF;
    float* s_obs  = sm + OFF_OBS;
    float* s_dg   = sm + OFF_DG;
    float* s_sc   = sm + OFF_SC;
    float* s_colw = sm + OFF_COLW;
    float* s_pool = sm + OFF_POOL;
    float* s_hr   = sm + OFF_HR;
    float* s_v    = sm + OFF_V;
    int*   s_edge = (int*)(sm + OFF_INT);
    int*   s_pred = s_edge + 40;

    const int tid = threadIdx.x;
    const int b0  = blockIdx.x * SPB;

    // ---------- Stage 0: inputs ----------
    for (int i = tid; i < SPB*85; i += NT) {
        int s = i / 85, c = i - 85*s;
        s_obs[s*88 + c] = obs[(size_t)(b0+s)*85 + c];
    }
    for (int i = tid; i < SPB*30; i += NT) {
        int s = i / 30, c = i - 30*s;
        s_dg[s*32 + c] = g[(size_t)(b0+s)*30 + c] - ag[(size_t)(b0+s)*30 + c];
    }
    if (tid < 40) s_edge[tid] = edges[tid];
    if (tid < 60) s_pred[tid] = pred_ids[tid];
    __syncthreads();

    for (int i = tid; i < SPB*NP*19; i += NT) {
        int s = i / (NP*19); int rem = i - s*NP*19;
        int p = rem / 19;    int c = rem - 19*p;
        float val;
        if (c < 10)      val = s_obs[s*88 + c];
        else if (c < 13) val = s_dg[s*32 + s_pred[p*3 + (c-10)]];
        else if (c < 16) val = s_obs[s*88 + 10 + s_edge[p*2]   * 15 + (c-13)];
        else             val = s_obs[s*88 + 10 + s_edge[p*2+1] * 15 + (c-16)];
        s_inp[(s*NP + p)*20 + c] = val;
    }
    // pad col 19 (read by float4 loads, multiplied by w1r[19]=unused -> must still be finite)
    for (int i = tid; i < SPB*NP; i += NT) s_inp[i*20 + 19] = 0.f;
    __syncthreads();

    // main GEMM thread mapping
    const int lane = tid & 31;
    const int wrp  = tid >> 5;
    const int ks   = lane & 1;                      // k-interleave bit
    const int cg   = ((wrp & 1) << 4) | (lane >> 1); // 0..31 -> cols 4cg..4cg+3
    const int rg   = wrp >> 1;                      // 0..3 -> rows 10rg..+9 (slots rg*12..)

#define FF5(ACC, HA, HB, HC)                                             \
    ACC[0][0]=ffma2(HA.x,w0,ACC[0][0]); ACC[0][1]=ffma2(HA.x,w1d,ACC[0][1]); \
    ACC[0][2]=ffma2(HA.x,w2d,ACC[0][2]); ACC[0][3]=ffma2(HA.x,w3d,ACC[0][3]); \
    ACC[1][0]=ffma2(HA.y,w0,ACC[1][0]); ACC[1][1]=ffma2(HA.y,w1d,ACC[1][1]); \
    ACC[1][2]=ffma2(HA.y,w2d,ACC[1][2]); ACC[1][3]=ffma2(HA.y,w3d,ACC[1][3]); \
    ACC[2][0]=ffma2(HB.x,w0,ACC[2][0]); ACC[2][1]=ffma2(HB.x,w1d,ACC[2][1]); \
    ACC[2][2]=ffma2(HB.x,w2d,ACC[2][2]); ACC[2][3]=ffma2(HB.x,w3d,ACC[2][3]); \
    ACC[3][0]=ffma2(HB.y,w0,ACC[3][0]); ACC[3][1]=ffma2(HB.y,w1d,ACC[3][1]); \
    ACC[3][2]=ffma2(HB.y,w2d,ACC[3][2]); ACC[3][3]=ffma2(HB.y,w3d,ACC[3][3]); \
    ACC[4][0]=ffma2(HC,w0,ACC[4][0]);   ACC[4][1]=ffma2(HC,w1d,ACC[4][1]);   \
    ACC[4][2]=ffma2(HC,w2d,ACC[4][2]);  ACC[4][3]=ffma2(HC,w3d,ACC[4][3]);

    // ---------- Stage 1+2 fused: ef = relu(relu(inp@W1+b1) @ W2 + b2) ----------
    {
        u64t acc[5][4];
        #pragma unroll
        for (int j = 0; j < 5; j++)
            #pragma unroll
            for (int c = 0; c < 4; c++) acc[j][c] = 0ull;

        for (int cc = 0; cc < 8; cc++) {
            // stage1: build hT for 32 k-columns of this chunk
            {
                int hc = tid & 31, g8 = tid >> 5;
                int hcol = cc*32 + hc;
                float w1r[19];
                #pragma unroll
                for (int c = 0; c < 19; c++) w1r[c] = W1[c*256 + hcol];
                float bb = b1[hcol];
                int slotbase = (g8 >> 1)*12 + 5*(g8 & 1);
                #pragma unroll
                for (int r = 0; r < 5; r++) {
                    int row = g8*5 + r;
                    const float4* ip = (const float4*)(s_inp + row*20);
                    float4 i0 = ip[0], i1 = ip[1], i2 = ip[2], i3 = ip[3], i4 = ip[4];
                    float a = bb;
                    a = fmaf(i0.x, w1r[0], a);  a = fmaf(i0.y, w1r[1], a);
                    a = fmaf(i0.z, w1r[2], a);  a = fmaf(i0.w, w1r[3], a);
                    a = fmaf(i1.x, w1r[4], a);  a = fmaf(i1.y, w1r[5], a);
                    a = fmaf(i1.z, w1r[6], a);  a = fmaf(i1.w, w1r[7], a);
                    a = fmaf(i2.x, w1r[8], a);  a = fmaf(i2.y, w1r[9], a);
                    a = fmaf(i2.z, w1r[10], a); a = fmaf(i2.w, w1r[11], a);
                    a = fmaf(i3.x, w1r[12], a); a = fmaf(i3.y, w1r[13], a);
                    a = fmaf(i3.z, w1r[14], a); a = fmaf(i3.w, w1r[15], a);
                    a = fmaf(i4.x, w1r[16], a); a = fmaf(i4.y, w1r[17], a);
                    a = fmaf(i4.z, w1r[18], a);
                    s_hT[hc*LD + slotbase + r] = fmaxf(a, 0.f);
                }
            }
            // stage W2 chunk (32 x 128)
            {
                const float4* src = (const float4*)(W2 + cc*4096);
                float4* dst = (float4*)s_wbuf;
                dst[tid] = src[tid];
                dst[tid + 256] = src[tid + 256];
                dst[tid + 512] = src[tid + 512];
                dst[tid + 768] = src[tid + 768];
            }
            __syncthreads();
            #pragma unroll 4
            for (int kk = 0; kk < 16; kk++) {
                int k2 = 2*kk + ks;
                const float* hb = s_hT + k2*LD + rg*12;
                ulonglong2 hA = *(const ulonglong2*)hb;
                ulonglong2 hB = *(const ulonglong2*)(hb + 4);
                u64t hC = *(const u64t*)(hb + 8);
                float4 wv = *(const float4*)(s_wbuf + k2*128 + 4*cg);
                u64t w0 = dup2(wv.x), w1d = dup2(wv.y), w2d = dup2(wv.z), w3d = dup2(wv.w);
                FF5(acc, hA, hB, hC)
            }
            __syncthreads();
        }
        // k-split reduce across lane pairs
        #pragma unroll
        for (int j = 0; j < 5; j++)
            #pragma unroll
            for (int c = 0; c < 4; c++) {
                u64t o = __shfl_xor_sync(0xffffffffu, acc[j][c], 1);
                acc[j][c] = add2(acc[j][c], o);
            }
        // epilogue: bias + relu, store transposed into efT (even lanes)
        if (ks == 0) {
            float4 bb = *(const float4*)(b2 + 4*cg);
            float barr[4] = {bb.x, bb.y, bb.z, bb.w};
            #pragma unroll
            for (int c = 0; c < 4; c++)
                #pragma unroll
                for (int j = 0; j < 5; j++) {
                    float2 e = unpk(acc[j][c]);
                    e.x = fmaxf(e.x + barr[c], 0.f);
                    e.y = fmaxf(e.y + barr[c], 0.f);
                    *(float2*)(s_efT + (4*cg + c)*LD + rg*12 + 2*j) = e;
                }
        }
    }

    // ---------- Stage 3: q/k/v = ef @ W{q,k,v} + b ----------
    for (int m = 0; m < 3; m++) {
        const float* Wmat = (m == 0) ? Wq : ((m == 1) ? Wk : Wv);
        const float* bvec = (m == 0) ? bq : ((m == 1) ? bk : bv);
        u64t acc[5][4];
        #pragma unroll
        for (int j = 0; j < 5; j++)
            #pragma unroll
            for (int c = 0; c < 4; c++) acc[j][c] = 0ull;

        for (int cc = 0; cc < 2; cc++) {
            {
                const float4* src = (const float4*)(Wmat + cc*8192);
                float4* dst = (float4*)s_wbuf;
                #pragma unroll
                for (int i = 0; i < 8; i++) dst[tid + i*256] = src[tid + i*256];
            }
            __syncthreads();
            #pragma unroll 4
            for (int kk = 0; kk < 32; kk++) {
                int k2 = 2*kk + ks;
                const float* eb = s_efT + (cc*64 + k2)*LD + rg*12;
                ulonglong2 hA = *(const ulonglong2*)eb;
                ulonglong2 hB = *(const ulonglong2*)(eb + 4);
                u64t hC = *(const u64t*)(eb + 8);
                float4 wv = *(const float4*)(s_wbuf + k2*128 + 4*cg);
                u64t w0 = dup2(wv.x), w1d = dup2(wv.y), w2d = dup2(wv.z), w3d = dup2(wv.w);
                FF5(acc, hA, hB, hC)
            }
            __syncthreads();
        }
        #pragma unroll
        for (int j = 0; j < 5; j++)
            #pragma unroll
            for (int c = 0; c < 4; c++) {
                u64t o = __shfl_xor_sync(0xffffffffu, acc[j][c], 1);
                acc[j][c] = add2(acc[j][c], o);
            }
        if (ks == 0) {
            float* dst = (m == 0) ? s_q : ((m == 1) ? s_kk : s_v);
            float4 bb = *(const float4*)(bvec + 4*cg);
            float barr[4] = {bb.x, bb.y, bb.z, bb.w};
            #pragma unroll
            for (int c = 0; c < 4; c++)
                #pragma unroll
                for (int j = 0; j < 5; j++) {
                    float2 e = unpk(acc[j][c]);
                    int row = rg*10 + 2*j;
                    dst[ row     *128 + 4*cg + c] = e.x + barr[c];
                    dst[(row + 1)*128 + 4*cg + c] = e.y + barr[c];
                }
        }
    }
    __syncthreads();

    // ---------- Stage 4: scores = q @ k^T / sqrt(128), 2x2 tiles ----------
    if (tid < 200) {
        int s  = tid / 100, t2 = tid % 100;
        int p0 = (t2 / 10) * 2, r0 = (t2 % 10) * 2;
        const u64t* qA = (const u64t*)(s_q  + (s*20 + p0)*128);
        const u64t* qB = (const u64t*)(s_q  + (s*20 + p0 + 1)*128);
        const u64t* kA = (const u64t*)(s_kk + (s*20 + r0)*128);
        const u64t* kB = (const u64t*)(s_kk + (s*20 + r0 + 1)*128);
        u64t a00 = 0ull, a01 = 0ull, a10 = 0ull, a11 = 0ull;
        #pragma unroll 8
        for (int i = 0; i < 64; i++) {
            u64t q0 = qA[i], q1 = qB[i], k0 = kA[i], k1 = kB[i];
            a00 = ffma2(q0, k0, a00); a01 = ffma2(q0, k1, a01);
            a10 = ffma2(q1, k0, a10); a11 = ffma2(q1, k1, a11);
        }
        const float scl = 0.088388347648318447f;
        float2 f;
        f = unpk(a00); s_sc[(s*20 + p0    )*NP + r0    ] = (f.x + f.y) * scl;
        f = unpk(a01); s_sc[(s*20 + p0    )*NP + r0 + 1] = (f.x + f.y) * scl;
        f = unpk(a10); s_sc[(s*20 + p0 + 1)*NP + r0    ] = (f.x + f.y) * scl;
        f = unpk(a11); s_sc[(s*20 + p0 + 1)*NP + r0 + 1] = (f.x + f.y) * scl;
    }
    __syncthreads();

    // ---------- Stage 5: softmax + column sums ----------
    if (tid < SPB*NP) {
        float* row = &s_sc[tid*NP];
        float mx = row[0];
        #pragma unroll
        for (int r = 1; r < NP; r++) mx = fmaxf(mx, row[r]);
        float sum = 0.f;
        #pragma unroll
        for (int r = 0; r < NP; r++) { float e = __expf(row[r] - mx); row[r] = e; sum += e; }
        float inv = 1.f / sum;
        #pragma unroll
        for (int r = 0; r < NP; r++) row[r] *= inv;
    }
    __syncthreads();
    if (tid < SPB*NP) {
        int s = tid / NP, r = tid - NP*s;
        float a = 0.f;
        #pragma unroll
        for (int p = 0; p < NP; p++) a += s_sc[(s*NP + p)*NP + r];
        s_colw[tid] = a;
    }
    __syncthreads();

    // ---------- Stage 6: pooled = colw @ v ----------
    {
        int s = tid >> 7, d = tid & 127;
        float a = 0.f;
        #pragma unroll
        for (int r = 0; r < NP; r++) a = fmaf(s_colw[s*NP + r], s_v[(s*NP + r)*128 + d], a);
        s_pool[s*128 + d] = a;
    }
    __syncthreads();

    // ---------- Stage 7: hr = relu(pooled @ Wr + br) ----------
    {
        float a0 = br[tid], a1 = a0;
        #pragma unroll 8
        for (int d = 0; d < 128; d++) {
            float w = Wr[d*256 + tid];
            a0 = fmaf(s_pool[d],       w, a0);
            a1 = fmaf(s_pool[128 + d], w, a1);
        }
        s_hr[tid]       = fmaxf(a0, 0.f);
        s_hr[256 + tid] = fmaxf(a1, 0.f);
    }
    __syncthreads();

    // ---------- Stage 8: heads ----------
    {
        int w = tid >> 5, ln = tid & 31;
        for (int o = w; o < 16; o += 8) {
            int s = o >> 3, head = (o >> 2) & 1, a = o & 3;
            const float* Wh = head ? Ws : Wm;
            float acc8 = 0.f;
            #pragma unroll
            for (int j = ln; j < 256; j += 32)
                acc8 = fmaf(s_hr[s*256 + j], Wh[j*4 + a], acc8);
            #pragma unroll
            for (int off = 16; off > 0; off >>= 1)
                acc8 += __shfl_xor_sync(0xffffffffu, acc8, off);
            if (ln == 0) {
                float val = acc8 + (head ? bs[a] : bm[a]);
                size_t bg = (size_t)(b0 + s);
                if (head) {
                    val = fminf(fmaxf(val, -20.f), 2.f);
                    out[(size_t)B*4 + bg*4 + a] = val;
                } else {
                    out[bg*4 + a] = val;
                }
            }
        }
    }
}

extern "C" void kernel_launch(void* const* d_in, const int* in_sizes, int n_in,
                              void* d_out, int out_size) {
    const float* obs = (const float*)d_in[0];
    const float* ag  = (const float*)d_in[1];
    const float* g   = (const float*)d_in[2];
    const float* W1  = (const float*)d_in[3];
    const float* b1  = (const float*)d_in[4];
    const float* W2  = (const float*)d_in[5];
    const float* b2  = (const float*)d_in[6];
    const float* Wq  = (const float*)d_in[7];
    const float* bq  = (const float*)d_in[8];
    const float* Wk  = (const float*)d_in[9];
    const float* bk  = (const float*)d_in[10];
    const float* Wv  = (const float*)d_in[11];
    const float* bv  = (const float*)d_in[12];
    const float* Wr  = (const float*)d_in[13];
    const float* br  = (const float*)d_in[14];
    const float* Wm  = (const float*)d_in[15];
    const float* bm  = (const float*)d_in[16];
    const float* Ws  = (const float*)d_in[17];
    const float* bs  = (const float*)d_in[18];
    const int* edges    = (const int*)d_in[19];
    const int* pred_ids = (const int*)d_in[20];
    float* out = (float*)d_out;

    const int B = in_sizes[0] / 85;
    const size_t smem = (size_t)(SMEM_ELEMS + 100) * 4;  // 111,968 B -> 2 blocks/SM
    cudaFuncSetAttribute(actor_kernel, cudaFuncAttributeMaxDynamicSharedMemorySize, (int)smem);

    actor_kernel<<<B / SPB, NT, smem>>>(
        obs, ag, g, W1, b1, W2, b2, Wq, bq, Wk, bk, Wv, bv,
        Wr, br, Wm, bm, Ws, bs, edges, pred_ids, out, B);
}

// round 4
// speedup vs baseline: 2.1074x; 1.0017x over previous
#include <cuda_runtime.h>

#define NT   256
#define SPB  2
#define NP   20
#define LD   52     // hT/efT leading dim; rows in 4 groups of 10 at 12-slot stride

typedef unsigned long long u64t;

__device__ __forceinline__ u64t ffma2(u64t a, u64t b, u64t c) {
    u64t d;
    asm("fma.rn.f32x2 %0, %1, %2, %3;" : "=l"(d) : "l"(a), "l"(b), "l"(c));
    return d;
}
__device__ __forceinline__ u64t add2(u64t a, u64t b) {
    u64t d;
    asm("add.rn.f32x2 %0, %1, %2;" : "=l"(d) : "l"(a), "l"(b));
    return d;
}
__device__ __forceinline__ u64t dup2(float x) {
    u64t d;
    asm("mov.b64 %0, {%1, %1};" : "=l"(d) : "f"(x));
    return d;
}
__device__ __forceinline__ float2 unpk(u64t a) {
    float2 r;
    asm("mov.b64 {%0, %1}, %2;" : "=f"(r.x), "=f"(r.y) : "l"(a));
    return r;
}

// smem float offsets
#define OFF_INP   0        // 800  (40 x 20)
#define OFF_HT    800      // 1664 (32 x 52)   [overlay: sc 800, colw 48, pool 256]
#define OFF_EFT   2464     // 6656 (128 x 52)  [overlay: v 5120]
#define OFF_Q     9120     // 5120
#define OFF_K     14240    // 5120
#define OFF_WBUF  19360    // 8192
#define OFF_OBS   27552    // 176
#define OFF_DG    27728    // 64
#define OFF_INT   27792    // 100 ints
#define SMEM_ELEMS 27892
// overlays
#define OFF_SC    OFF_HT          // 800
#define OFF_COLW  (OFF_HT + 800)  // 48
#define OFF_POOL  (OFF_HT + 848)  // 256
#define OFF_HR    0               // 512 (over inp)
#define OFF_V     OFF_EFT         // 5120 (over efT)

__global__ __launch_bounds__(NT, 2)
void actor_kernel(
    const float* __restrict__ obs, const float* __restrict__ ag, const float* __restrict__ g,
    const float* __restrict__ W1, const float* __restrict__ b1,
    const float* __restrict__ W2, const float* __restrict__ b2,
    const float* __restrict__ Wq, const float* __restrict__ bq,
    const float* __restrict__ Wk, const float* __restrict__ bk,
    const float* __restrict__ Wv, const float* __restrict__ bv,
    const float* __restrict__ Wr, const float* __restrict__ br,
    const float* __restrict__ Wm, const float* __restrict__ bm,
    const float* __restrict__ Ws, const float* __restrict__ bs,
    const int* __restrict__ edges, const int* __restrict__ pred_ids,
    float* __restrict__ out, int B)
{
    extern __shared__ float sm[];
    float* s_inp  = sm + OFF_INP;
    float* s_hT   = sm + OFF_HT;
    float* s_efT  = sm + OFF_EFT;
    float* s_q    = sm + OFF_Q;
    float* s_kk   = sm + OFF_K;
    float* s_wbuf = sm + OFF_WBUF;
    float* s_obs  = sm + OFF_OBS;
    float* s_dg   = sm + OFF_DG;
    float* s_sc   = sm + OFF_SC;
    float* s_colw = sm + OFF_COLW;
    float* s_pool = sm + OFF_POOL;
    float* s_hr   = sm + OFF_HR;
    float* s_v    = sm + OFF_V;
    int*   s_edge = (int*)(sm + OFF_INT);
    int*   s_pred = s_edge + 40;

    const int tid = threadIdx.x;
    const int b0  = blockIdx.x * SPB;

    // ---------- Stage 0: inputs ----------
    for (int i = tid; i < SPB*85; i += NT) {
        int s = i / 85, c = i - 85*s;
        s_obs[s*88 + c] = obs[(size_t)(b0+s)*85 + c];
    }
    for (int i = tid; i < SPB*30; i += NT) {
        int s = i / 30, c = i - 30*s;
        s_dg[s*32 + c] = g[(size_t)(b0+s)*30 + c] - ag[(size_t)(b0+s)*30 + c];
    }
    if (tid < 40) s_edge[tid] = edges[tid];
    if (tid < 60) s_pred[tid] = pred_ids[tid];
    __syncthreads();

    for (int i = tid; i < SPB*NP*19; i += NT) {
        int s = i / (NP*19); int rem = i - s*NP*19;
        int p = rem / 19;    int c = rem - 19*p;
        float val;
        if (c < 10)      val = s_obs[s*88 + c];
        else if (c < 13) val = s_dg[s*32 + s_pred[p*3 + (c-10)]];
        else if (c < 16) val = s_obs[s*88 + 10 + s_edge[p*2]   * 15 + (c-13)];
        else             val = s_obs[s*88 + 10 + s_edge[p*2+1] * 15 + (c-16)];
        s_inp[(s*NP + p)*20 + c] = val;
    }
    // pad col 19 (read by float4 loads, multiplied by w1r[19]=unused -> must still be finite)
    for (int i = tid; i < SPB*NP; i += NT) s_inp[i*20 + 19] = 0.f;
    __syncthreads();

    // main GEMM thread mapping
    const int lane = tid & 31;
    const int wrp  = tid >> 5;
    const int ks   = lane & 1;                      // k-interleave bit
    const int cg   = ((wrp & 1) << 4) | (lane >> 1); // 0..31 -> cols 4cg..4cg+3
    const int rg   = wrp >> 1;                      // 0..3 -> rows 10rg..+9 (slots rg*12..)

#define FF5(ACC, HA, HB, HC)                                             \
    ACC[0][0]=ffma2(HA.x,w0,ACC[0][0]); ACC[0][1]=ffma2(HA.x,w1d,ACC[0][1]); \
    ACC[0][2]=ffma2(HA.x,w2d,ACC[0][2]); ACC[0][3]=ffma2(HA.x,w3d,ACC[0][3]); \
    ACC[1][0]=ffma2(HA.y,w0,ACC[1][0]); ACC[1][1]=ffma2(HA.y,w1d,ACC[1][1]); \
    ACC[1][2]=ffma2(HA.y,w2d,ACC[1][2]); ACC[1][3]=ffma2(HA.y,w3d,ACC[1][3]); \
    ACC[2][0]=ffma2(HB.x,w0,ACC[2][0]); ACC[2][1]=ffma2(HB.x,w1d,ACC[2][1]); \
    ACC[2][2]=ffma2(HB.x,w2d,ACC[2][2]); ACC[2][3]=ffma2(HB.x,w3d,ACC[2][3]); \
    ACC[3][0]=ffma2(HB.y,w0,ACC[3][0]); ACC[3][1]=ffma2(HB.y,w1d,ACC[3][1]); \
    ACC[3][2]=ffma2(HB.y,w2d,ACC[3][2]); ACC[3][3]=ffma2(HB.y,w3d,ACC[3][3]); \
    ACC[4][0]=ffma2(HC,w0,ACC[4][0]);   ACC[4][1]=ffma2(HC,w1d,ACC[4][1]);   \
    ACC[4][2]=ffma2(HC,w2d,ACC[4][2]);  ACC[4][3]=ffma2(HC,w3d,ACC[4][3]);

    // ---------- Stage 1+2 fused: ef = relu(relu(inp@W1+b1) @ W2 + b2) ----------
    {
        u64t acc[5][4];
        #pragma unroll
        for (int j = 0; j < 5; j++)
            #pragma unroll
            for (int c = 0; c < 4; c++) acc[j][c] = 0ull;

        for (int cc = 0; cc < 8; cc++) {
            // stage1: build hT for 32 k-columns of this chunk
            {
                int hc = tid & 31, g8 = tid >> 5;
                int hcol = cc*32 + hc;
                float w1r[19];
                #pragma unroll
                for (int c = 0; c < 19; c++) w1r[c] = W1[c*256 + hcol];
                float bb = b1[hcol];
                int slotbase = (g8 >> 1)*12 + 5*(g8 & 1);
                #pragma unroll
                for (int r = 0; r < 5; r++) {
                    int row = g8*5 + r;
                    const float4* ip = (const float4*)(s_inp + row*20);
                    float4 i0 = ip[0], i1 = ip[1], i2 = ip[2], i3 = ip[3], i4 = ip[4];
                    float a = bb;
                    a = fmaf(i0.x, w1r[0], a);  a = fmaf(i0.y, w1r[1], a);
                    a = fmaf(i0.z, w1r[2], a);  a = fmaf(i0.w, w1r[3], a);
                    a = fmaf(i1.x, w1r[4], a);  a = fmaf(i1.y, w1r[5], a);
                    a = fmaf(i1.z, w1r[6], a);  a = fmaf(i1.w, w1r[7], a);
                    a = fmaf(i2.x, w1r[8], a);  a = fmaf(i2.y, w1r[9], a);
                    a = fmaf(i2.z, w1r[10], a); a = fmaf(i2.w, w1r[11], a);
                    a = fmaf(i3.x, w1r[12], a); a = fmaf(i3.y, w1r[13], a);
                    a = fmaf(i3.z, w1r[14], a); a = fmaf(i3.w, w1r[15], a);
                    a = fmaf(i4.x, w1r[16], a); a = fmaf(i4.y, w1r[17], a);
                    a = fmaf(i4.z, w1r[18], a);
                    s_hT[hc*LD + slotbase + r] = fmaxf(a, 0.f);
                }
            }
            // stage W2 chunk (32 x 128)
            {
                const float4* src = (const float4*)(W2 + cc*4096);
                float4* dst = (float4*)s_wbuf;
                dst[tid] = src[tid];
                dst[tid + 256] = src[tid + 256];
                dst[tid + 512] = src[tid + 512];
                dst[tid + 768] = src[tid + 768];
            }
            __syncthreads();
            #pragma unroll 4
            for (int kk = 0; kk < 16; kk++) {
                int k2 = 2*kk + ks;
                const float* hb = s_hT + k2*LD + rg*12;
                ulonglong2 hA = *(const ulonglong2*)hb;
                ulonglong2 hB = *(const ulonglong2*)(hb + 4);
                u64t hC = *(const u64t*)(hb + 8);
                float4 wv = *(const float4*)(s_wbuf + k2*128 + 4*cg);
                u64t w0 = dup2(wv.x), w1d = dup2(wv.y), w2d = dup2(wv.z), w3d = dup2(wv.w);
                FF5(acc, hA, hB, hC)
            }
            __syncthreads();
        }
        // k-split reduce across lane pairs
        #pragma unroll
        for (int j = 0; j < 5; j++)
            #pragma unroll
            for (int c = 0; c < 4; c++) {
                u64t o = __shfl_xor_sync(0xffffffffu, acc[j][c], 1);
                acc[j][c] = add2(acc[j][c], o);
            }
        // epilogue: bias + relu, store transposed into efT (even lanes)
        if (ks == 0) {
            float4 bb = *(const float4*)(b2 + 4*cg);
            float barr[4] = {bb.x, bb.y, bb.z, bb.w};
            #pragma unroll
            for (int c = 0; c < 4; c++)
                #pragma unroll
                for (int j = 0; j < 5; j++) {
                    float2 e = unpk(acc[j][c]);
                    e.x = fmaxf(e.x + barr[c], 0.f);
                    e.y = fmaxf(e.y + barr[c], 0.f);
                    *(float2*)(s_efT + (4*cg + c)*LD + rg*12 + 2*j) = e;
                }
        }
    }

    // ---------- Stage 3: q/k/v = ef @ W{q,k,v} + b ----------
    for (int m = 0; m < 3; m++) {
        const float* Wmat = (m == 0) ? Wq : ((m == 1) ? Wk : Wv);
        const float* bvec = (m == 0) ? bq : ((m == 1) ? bk : bv);
        u64t acc[5][4];
        #pragma unroll
        for (int j = 0; j < 5; j++)
            #pragma unroll
            for (int c = 0; c < 4; c++) acc[j][c] = 0ull;

        for (int cc = 0; cc < 2; cc++) {
            {
                const float4* src = (const float4*)(Wmat + cc*8192);
                float4* dst = (float4*)s_wbuf;
                #pragma unroll
                for (int i = 0; i < 8; i++) dst[tid + i*256] = src[tid + i*256];
            }
            __syncthreads();
            #pragma unroll 4
            for (int kk = 0; kk < 32; kk++) {
                int k2 = 2*kk + ks;
                const float* eb = s_efT + (cc*64 + k2)*LD + rg*12;
                ulonglong2 hA = *(const ulonglong2*)eb;
                ulonglong2 hB = *(const ulonglong2*)(eb + 4);
                u64t hC = *(const u64t*)(eb + 8);
                float4 wv = *(const float4*)(s_wbuf + k2*128 + 4*cg);
                u64t w0 = dup2(wv.x), w1d = dup2(wv.y), w2d = dup2(wv.z), w3d = dup2(wv.w);
                FF5(acc, hA, hB, hC)
            }
            __syncthreads();
        }
        #pragma unroll
        for (int j = 0; j < 5; j++)
            #pragma unroll
            for (int c = 0; c < 4; c++) {
                u64t o = __shfl_xor_sync(0xffffffffu, acc[j][c], 1);
                acc[j][c] = add2(acc[j][c], o);
            }
        if (ks == 0) {
            float* dst = (m == 0) ? s_q : ((m == 1) ? s_kk : s_v);
            float4 bb = *(const float4*)(bvec + 4*cg);
            float barr[4] = {bb.x, bb.y, bb.z, bb.w};
            #pragma unroll
            for (int c = 0; c < 4; c++)
                #pragma unroll
                for (int j = 0; j < 5; j++) {
                    float2 e = unpk(acc[j][c]);
                    int row = rg*10 + 2*j;
                    dst[ row     *128 + 4*cg + c] = e.x + barr[c];
                    dst[(row + 1)*128 + 4*cg + c] = e.y + barr[c];
                }
        }
    }
    __syncthreads();

    // ---------- Stage 4: scores = q @ k^T / sqrt(128), 2x2 tiles ----------
    if (tid < 200) {
        int s  = tid / 100, t2 = tid % 100;
        int p0 = (t2 / 10) * 2, r0 = (t2 % 10) * 2;
        const u64t* qA = (const u64t*)(s_q  + (s*20 + p0)*128);
        const u64t* qB = (const u64t*)(s_q  + (s*20 + p0 + 1)*128);
        const u64t* kA = (const u64t*)(s_kk + (s*20 + r0)*128);
        const u64t* kB = (const u64t*)(s_kk + (s*20 + r0 + 1)*128);
        u64t a00 = 0ull, a01 = 0ull, a10 = 0ull, a11 = 0ull;
        #pragma unroll 8
        for (int i = 0; i < 64; i++) {
            u64t q0 = qA[i], q1 = qB[i], k0 = kA[i], k1 = kB[i];
            a00 = ffma2(q0, k0, a00); a01 = ffma2(q0, k1, a01);
            a10 = ffma2(q1, k0, a10); a11 = ffma2(q1, k1, a11);
        }
        const float scl = 0.088388347648318447f;
        float2 f;
        f = unpk(a00); s_sc[(s*20 + p0    )*NP + r0    ] = (f.x + f.y) * scl;
        f = unpk(a01); s_sc[(s*20 + p0    )*NP + r0 + 1] = (f.x + f.y) * scl;
        f = unpk(a10); s_sc[(s*20 + p0 + 1)*NP + r0    ] = (f.x + f.y) * scl;
        f = unpk(a11); s_sc[(s*20 + p0 + 1)*NP + r0 + 1] = (f.x + f.y) * scl;
    }
    __syncthreads();

    // ---------- Stage 5: softmax + column sums ----------
    if (tid < SPB*NP) {
        float* row = &s_sc[tid*NP];
        float mx = row[0];
        #pragma unroll
        for (int r = 1; r < NP; r++) mx = fmaxf(mx, row[r]);
        float sum = 0.f;
        #pragma unroll
        for (int r = 0; r < NP; r++) { float e = __expf(row[r] - mx); row[r] = e; sum += e; }
        float inv = 1.f / sum;
        #pragma unroll
        for (int r = 0; r < NP; r++) row[r] *= inv;
    }
    __syncthreads();
    if (tid < SPB*NP) {
        int s = tid / NP, r = tid - NP*s;
        float a = 0.f;
        #pragma unroll
        for (int p = 0; p < NP; p++) a += s_sc[(s*NP + p)*NP + r];
        s_colw[tid] = a;
    }
    __syncthreads();

    // ---------- Stage 6: pooled = colw @ v ----------
    {
        int s = tid >> 7, d = tid & 127;
        float a = 0.f;
        #pragma unroll
        for (int r = 0; r < NP; r++) a = fmaf(s_colw[s*NP + r], s_v[(s*NP + r)*128 + d], a);
        s_pool[s*128 + d] = a;
    }
    __syncthreads();

    // ---------- Stage 7: hr = relu(pooled @ Wr + br) ----------
    {
        float a0 = br[tid], a1 = a0;
        #pragma unroll 8
        for (int d = 0; d < 128; d++) {
            float w = Wr[d*256 + tid];
            a0 = fmaf(s_pool[d],       w, a0);
            a1 = fmaf(s_pool[128 + d], w, a1);
        }
        s_hr[tid]       = fmaxf(a0, 0.f);
        s_hr[256 + tid] = fmaxf(a1, 0.f);
    }
    __syncthreads();

    // ---------- Stage 8: heads ----------
    {
        int w = tid >> 5, ln = tid & 31;
        for (int o = w; o < 16; o += 8) {
            int s = o >> 3, head = (o >> 2) & 1, a = o & 3;
            const float* Wh = head ? Ws : Wm;
            float acc8 = 0.f;
            #pragma unroll
            for (int j = ln; j < 256; j += 32)
                acc8 = fmaf(s_hr[s*256 + j], Wh[j*4 + a], acc8);
            #pragma unroll
            for (int off = 16; off > 0; off >>= 1)
                acc8 += __shfl_xor_sync(0xffffffffu, acc8, off);
            if (ln == 0) {
                float val = acc8 + (head ? bs[a] : bm[a]);
                size_t bg = (size_t)(b0 + s);
                if (head) {
                    val = fminf(fmaxf(val, -20.f), 2.f);
                    out[(size_t)B*4 + bg*4 + a] = val;
                } else {
                    out[bg*4 + a] = val;
                }
            }
        }
    }
}

extern "C" void kernel_launch(void* const* d_in, const int* in_sizes, int n_in,
                              void* d_out, int out_size) {
    const float* obs = (const float*)d_in[0];
    const float* ag  = (const float*)d_in[1];
    const float* g   = (const float*)d_in[2];
    const float* W1  = (const float*)d_in[3];
    const float* b1  = (const float*)d_in[4];
    const float* W2  = (const float*)d_in[5];
    const float* b2  = (const float*)d_in[6];
    const float* Wq  = (const float*)d_in[7];
    const float* bq  = (const float*)d_in[8];
    const float* Wk  = (const float*)d_in[9];
    const float* bk  = (const float*)d_in[10];
    const float* Wv  = (const float*)d_in[11];
    const float* bv  = (const float*)d_in[12];
    const float* Wr  = (const float*)d_in[13];
    const float* br  = (const float*)d_in[14];
    const float* Wm  = (const float*)d_in[15];
    const float* bm  = (const float*)d_in[16];
    const float* Ws  = (const float*)d_in[17];
    const float* bs  = (const float*)d_in[18];
    const int* edges    = (const int*)d_in[19];
    const int* pred_ids = (const int*)d_in[20];
    float* out = (float*)d_out;

    const int B = in_sizes[0] / 85;
    const size_t smem = (size_t)(SMEM_ELEMS + 100) * 4;  // 111,968 B -> 2 blocks/SM
    cudaFuncSetAttribute(actor_kernel, cudaFuncAttributeMaxDynamicSharedMemorySize, (int)smem);

    actor_kernel<<<B / SPB, NT, smem>>>(
        obs, ag, g, W1, b1, W2, b2, Wq, bq, Wk, bk, Wv, bv,
        Wr, br, Wm, bm, Ws, bs, edges, pred_ids, out, B);
}